// round 1
// baseline (speedup 1.0000x reference)
#include <cuda_runtime.h>
#include <cstdint>
#include <cstddef>

// Problem constants (fixed by setup_inputs)
#define N_ 8
#define C_ 256
#define H_ 64
#define W_ 64
#define A_ 9
#define BS_ 8
#define F_ 8
#define K_ 64
#define M_ (A_*N_*K_)   // 4608

// Scratch (static device globals; no runtime allocation)
__device__ float g_reg[N_*A_*F_*F_];           // 4608 conv outputs
__device__ float g_featT[(size_t)N_*H_*W_*C_]; // NHWC transposed feature (33.5 MB)
__device__ float g_roisb[(size_t)M_*C_];       // sampled rois_feature_b
__device__ float g_tmp[(size_t)M_*C_];         // intermediate rois output

// ---------------------------------------------------------------------------
// Kernel 1: zero the conv accumulator (atomics accumulate into it每 launch)
// ---------------------------------------------------------------------------
__global__ void zero_reg_kernel() {
    int i = blockIdx.x * blockDim.x + threadIdx.x;
    if (i < N_*A_*F_*F_) g_reg[i] = 0.f;
}

// ---------------------------------------------------------------------------
// Kernel 2: NCHW -> NHWC transpose of feature_b (for coalesced bilinear gathers)
// ---------------------------------------------------------------------------
__global__ void transpose_kernel(const float* __restrict__ feat) {
    __shared__ float tile[32][33];
    int n = blockIdx.z, ct = blockIdx.y, hwt = blockIdx.x;
    int tx = threadIdx.x, ty = threadIdx.y;
    const float* src = feat + (size_t)n * C_ * H_ * W_;
    float* dst = g_featT + (size_t)n * H_ * W_ * C_;
    #pragma unroll
    for (int r = 0; r < 4; r++) {
        int c = ct*32 + ty + r*8;
        tile[ty + r*8][tx] = src[(size_t)c * 4096 + hwt*32 + tx];
    }
    __syncthreads();
    #pragma unroll
    for (int r = 0; r < 4; r++) {
        int hw = hwt*32 + ty + r*8;
        dst[(size_t)hw * 256 + ct*32 + tx] = tile[tx][ty + r*8];
    }
}

// ---------------------------------------------------------------------------
// Kernel 3: stride-8 8x8 "VALID" conv  reg[n,aa,fy,fx] += sum_c,ky,kx feat*W
// Block = (cc in 0..7 [32-channel slice], fyh in 0..1, n). 256 threads =
// (ky 0..7) x (cl 0..31). W slice + one fy patch band staged in smem.
// ---------------------------------------------------------------------------
#define WS 68                      // padded W row stride (floats)
#define PS 516                     // padded patch per-channel stride (floats)
#define CONV_SMEM ((9*32*WS + 32*PS) * 4)

__global__ __launch_bounds__(256, 1)
void conv_kernel(const float* __restrict__ feat, const float* __restrict__ Wreg) {
    extern __shared__ float sm[];
    float* Wsl   = sm;               // [9][32][WS]
    float* patch = sm + 9*32*WS;     // [32][PS] (8 rows x 64 cols used)
    int cc  = blockIdx.x;
    int fyh = blockIdx.y;
    int n   = blockIdx.z;
    int tid = threadIdx.x;
    int ky = tid >> 5, cl = tid & 31;

    // Stage W slice: 9 * 32 * 64 floats, coalesced float4 loads
    #pragma unroll
    for (int it = 0; it < 18; it++) {
        int idx4 = it*256 + tid;       // 0..4607 float4s
        int aa  = idx4 >> 9;
        int rem = idx4 & 511;
        int clw = rem >> 4;
        int p4  = rem & 15;
        float4 v = *(const float4*)(Wreg + ((size_t)(aa*256 + cc*32 + clw)*64 + p4*4));
        *(float4*)(Wsl + (aa*32 + clw)*WS + p4*4) = v;
    }
    __syncthreads();

    for (int fy = fyh*4; fy < fyh*4 + 4; fy++) {
        // Stage patch band: 32c x 8 rows x 64 cols, coalesced float4
        #pragma unroll
        for (int it = 0; it < 16; it++) {
            int idx4 = it*256 + tid;   // 0..4095
            int clp = idx4 >> 7;
            int rem = idx4 & 127;
            int kyp = rem >> 4;
            int x4  = rem & 15;
            float4 v = *(const float4*)(feat +
                (((size_t)(n*256 + cc*32 + clp)*64 + fy*8 + kyp)*64 + x4*4));
            *(float4*)(patch + clp*PS + kyp*64 + x4*4) = v;
        }
        __syncthreads();

        // Each thread owns (cl, ky): its 64-pixel row band in registers
        float px[64];
        #pragma unroll
        for (int x4 = 0; x4 < 16; x4++) {
            float4 v = *(const float4*)(patch + cl*PS + ky*64 + x4*4);
            px[x4*4+0] = v.x; px[x4*4+1] = v.y; px[x4*4+2] = v.z; px[x4*4+3] = v.w;
        }
        #pragma unroll
        for (int aa = 0; aa < 9; aa++) {
            float w[8];
            float4 v0 = *(const float4*)(Wsl + (aa*32 + cl)*WS + ky*8);
            float4 v1 = *(const float4*)(Wsl + (aa*32 + cl)*WS + ky*8 + 4);
            w[0]=v0.x; w[1]=v0.y; w[2]=v0.z; w[3]=v0.w;
            w[4]=v1.x; w[5]=v1.y; w[6]=v1.z; w[7]=v1.w;
            #pragma unroll
            for (int fx = 0; fx < 8; fx++) {
                float acc = 0.f;
                #pragma unroll
                for (int kx = 0; kx < 8; kx++)
                    acc = fmaf(px[fx*8 + kx], w[kx], acc);
                // reduce over cl within warp
                #pragma unroll
                for (int off = 16; off; off >>= 1)
                    acc += __shfl_down_sync(0xffffffffu, acc, off);
                if (cl == 0)
                    atomicAdd(&g_reg[((n*9 + aa)*8 + fy)*8 + fx], acc);
            }
        }
        __syncthreads();
    }
}

// ---------------------------------------------------------------------------
// Kernel 4: tanh offset + bilinear sample from NHWC feature -> g_roisb
// Block = (k=fy*8+fx in 0..63, n). Thread = c (coalesced).
// ---------------------------------------------------------------------------
__global__ void sample_kernel(const float* __restrict__ breg) {
    int k = blockIdx.x;
    int n = blockIdx.y;
    int fy = k >> 3, fx = k & 7;
    int c = threadIdx.x;
    const float* ft = g_featT + (size_t)n * H_ * W_ * C_;
    #pragma unroll
    for (int aa = 0; aa < 9; aa++) {
        float rg = g_reg[((n*9 + aa)*8 + fy)*8 + fx] + breg[aa];
        float d  = 0.8f * tanhf(rg);
        float pxx = 3.5f + 8.f*fx + d;
        float pyy = 3.5f + 8.f*fy + d;
        float x0f = floorf(pxx), y0f = floorf(pyy);
        float wx = pxx - x0f, wy = pyy - y0f;
        int x0 = min(max((int)x0f, 0), 63);
        int x1 = min(x0 + 1, 63);
        int y0 = min(max((int)y0f, 0), 63);
        int y1 = min(y0 + 1, 63);
        float v00 = ft[(size_t)(y0*64 + x0)*256 + c];
        float v01 = ft[(size_t)(y0*64 + x1)*256 + c];
        float v10 = ft[(size_t)(y1*64 + x0)*256 + c];
        float v11 = ft[(size_t)(y1*64 + x1)*256 + c];
        float val = v00*(1.f-wx)*(1.f-wy) + v01*wx*(1.f-wy)
                  + v10*(1.f-wx)*wy       + v11*wx*wy;
        g_roisb[((size_t)(aa*8 + n)*64 + k)*256 + c] = val;
    }
}

// ---------------------------------------------------------------------------
// Kernel 5: rois_to_rois.  Group (n,aa,c): vectors a[64], b[64] over k,
// elements at X[(g*64 + k)*256 + c] with g = aa*8+n.
// out_j = b_j + (sum_i a_i 2^{a'_i b_j - m'})/(sum_i 2^{a'_i b_j - m'}) * ln2
// with a' = a*log2(e), m' = max(b_j a'max, b_j a'min)  (exact max, folded into FFMA).
// Grid: (jq 0..3, g 0..71). Thread = c. a' kept in 64 registers.
// ---------------------------------------------------------------------------
__global__ __launch_bounds__(256, 2)
void roisB_kernel(const float* __restrict__ Ain, const float* __restrict__ Bin,
                  float* __restrict__ Out) {
    int g  = blockIdx.y;   // aa*8 + n
    int jq = blockIdx.x;   // quarter of j
    int c  = threadIdx.x;
    const float* Ab = Ain + (size_t)g*64*256 + c;
    const float* Bb = Bin + (size_t)g*64*256 + c;
    float*       Ob = Out + (size_t)g*64*256 + c;

    float ap[64];
    float amax = -1e30f, amin = 1e30f;
    #pragma unroll
    for (int k = 0; k < 64; k++) {
        float v = Ab[k*256] * 1.4426950408889634f;  // a * log2(e)
        ap[k] = v;
        amax = fmaxf(amax, v);
        amin = fminf(amin, v);
    }

    #pragma unroll 1
    for (int j = jq*16; j < jq*16 + 16; j++) {
        float bj = Bb[j*256];
        float mm = fmaxf(bj*amax, bj*amin);   // exact max_i a'_i*bj
        float nmm = -mm;
        float s = 0.f, t = 0.f;
        #pragma unroll
        for (int i = 0; i < 64; i++) {
            float p = fmaf(ap[i], bj, nmm);   // <= 0 always
            float e;
            asm("ex2.approx.f32 %0, %1;" : "=f"(e) : "f"(p));
            s += e;
            t = fmaf(ap[i], e, t);
        }
        Ob[j*256] = bj + __fdividef(t * 0.6931471805599453f, s);
    }
}

// ---------------------------------------------------------------------------
// Launch sequence (default stream, graph-capturable; no sync, no alloc)
// ---------------------------------------------------------------------------
extern "C" void kernel_launch(void* const* d_in, const int* in_sizes, int n_in,
                              void* d_out, int out_size) {
    const float* rois_a = (const float*)d_in[1];
    const float* feat   = (const float*)d_in[2];
    const float* rois_c = (const float*)d_in[3];
    const float* Wreg   = (const float*)d_in[4];
    const float* breg   = (const float*)d_in[5];
    float* out = (float*)d_out;

    cudaFuncSetAttribute(conv_kernel,
                         cudaFuncAttributeMaxDynamicSharedMemorySize, CONV_SMEM);

    void *p_roisb = nullptr, *p_tmp = nullptr;
    cudaGetSymbolAddress(&p_roisb, g_roisb);
    cudaGetSymbolAddress(&p_tmp, g_tmp);

    zero_reg_kernel<<<18, 256>>>();
    transpose_kernel<<<dim3(128, 8, 8), dim3(32, 8)>>>(feat);
    conv_kernel<<<dim3(8, 2, 8), 256, CONV_SMEM>>>(feat, Wreg);
    sample_kernel<<<dim3(64, 8), 256>>>(breg);
    roisB_kernel<<<dim3(4, 72), 256>>>(rois_a, (const float*)p_roisb, (float*)p_tmp);
    roisB_kernel<<<dim3(4, 72), 256>>>((const float*)p_tmp, rois_c, out);
}